// round 7
// baseline (speedup 1.0000x reference)
#include <cuda_runtime.h>

typedef unsigned long long ULL;

// ---------------- scratch (static device globals; no allocation) ----------------
static __device__ float g_gi[500 * 1024 * 300];     // 614.4 MB: gi for current layer
static __device__ float g_buf0[500 * 1024 * 100];   // 204.8 MB: e0 / d0 sequence
static __device__ float g_d1[80 * 1024 * 100];      // decoder layer-1 outputs
static __device__ float g_decin[80 * 1024 * 26];    // embedded decoder inputs
static __device__ float g_h0[1024 * 100];           // h_enc0
static __device__ float g_h1[1024 * 100];           // h_enc1

// ---------------- f32x2 helpers ----------------
__device__ __forceinline__ ULL pack2(float lo, float hi) {
    ULL r;
    asm("mov.b64 %0, {%1, %2};" : "=l"(r) : "f"(lo), "f"(hi));
    return r;
}
__device__ __forceinline__ void unpack2(ULL v, float& lo, float& hi) {
    asm("mov.b64 {%0, %1}, %2;" : "=f"(lo), "=f"(hi) : "l"(v));
}
__device__ __forceinline__ void fma2(ULL& d, ULL a, ULL b) {
    asm("fma.rn.f32x2 %0, %1, %2, %0;" : "+l"(d) : "l"(a), "l"(b));
}

// ---------------- accurate activations (immune to fast-math flags) ----------------
__device__ __forceinline__ float exp_acc(float x) {
    float z = x * 1.4426950408889634f;
    float n = rintf(z);
    float r = fmaf(n, -0.693147182464599609375f, x);
    r = fmaf(n, 1.9046542121259336e-9f, r);
    float p = 1.9841270114e-4f;
    p = fmaf(p, r, 1.3888888877e-3f);
    p = fmaf(p, r, 8.3333337680e-3f);
    p = fmaf(p, r, 4.1666667908e-2f);
    p = fmaf(p, r, 1.6666667163e-1f);
    p = fmaf(p, r, 0.5f);
    p = fmaf(p, r, 1.0f);
    p = fmaf(p, r, 1.0f);
    int i = (int)n;
    float sc = __int_as_float((i + 127) << 23);
    return p * sc;
}
__device__ __forceinline__ float sigm(float x) {
    float xc = fminf(fmaxf(x, -30.0f), 30.0f);
    float s = exp_acc(-xc);
    return __fdiv_rn(1.0f, 1.0f + s);
}
__device__ __forceinline__ float tanh_acc(float x) {
    float ax = fabsf(x);
    float t;
    if (ax < 0.25f) {
        float x2 = x * x;
        float p = 0.021869488536155203f;
        p = fmaf(p, x2, -0.05396825396825397f);
        p = fmaf(p, x2, 0.13333333333333333f);
        p = fmaf(p, x2, -0.3333333333333333f);
        p = fmaf(p, x2, 1.0f);
        t = x * p;
    } else {
        float a = fminf(ax, 9.0f);
        float s = exp_acc(-2.0f * a);
        t = __fdiv_rn(1.0f - s, 1.0f + s);
        t = copysignf(t, x);
    }
    return t;
}

// ---------------- embedding gather ----------------
__global__ void k_embed(const int* __restrict__ tgt,
                        const float* __restrict__ emb,
                        float* __restrict__ out) {
    int idx = blockIdx.x * blockDim.x + threadIdx.x;
    const int total = 80 * 1024 * 26;
    if (idx < total) {
        int e  = idx % 26;
        int pb = idx / 26;
        int t = tgt[pb] & 63;
        out[idx] = emb[t * 26 + e];
    }
}

// ---------------- gi GEMM (2D register tile + distance-1 smem prefetch) ----------------
// Tile M=128 x N=64, 256 threads; thread-tile 8 rows x 4 cols.
// BITWISE: acc = bias; k-ascending fma chain (prefetch does not reorder arithmetic).
template <int K>
__global__ void __launch_bounds__(256) k_gemm(float* __restrict__ gi,
                                              const float* __restrict__ x,
                                              const float* __restrict__ W,
                                              const float* __restrict__ bih,
                                              const float* __restrict__ bhh) {
    const int MP = 132;   // A smem stride (floats)
    const int BP = 68;    // B smem stride
    extern __shared__ float sm[];
    float* As = sm;              // [K][132]  (k-major)  (+pad row at end)
    float* Bs = sm + (K + 1) * MP;  // [K][68] (+pad row at end)

    const int tid = threadIdx.x;
    const long n0 = (long)blockIdx.x * 128;
    const int  j0 = blockIdx.y * 64;

    for (int idx = tid; idx < 128 * K; idx += 256) {
        int m = idx / K, k = idx - m * K;
        As[k * MP + m] = x[(n0 + m) * K + k];
    }
    for (int idx = tid; idx < 64 * K; idx += 256) {
        int jj = idx / K, k = idx - jj * K;
        int j = j0 + jj;
        Bs[k * BP + jj] = (j < 300) ? W[j * K + k] : 0.0f;
    }
    __syncthreads();

    const int cx = tid & 15;      // 16 col-groups * 4 cols = 64
    const int ry = tid >> 4;      // 16 row-groups * 8 rows = 128

    ULL acc[4][4];
#pragma unroll
    for (int c = 0; c < 4; c++) {
        int j = j0 + cx * 4 + c;
        float bj = 0.0f;
        if (j < 300) bj = bih[j] + ((j < 200) ? bhh[j] : 0.0f);
        ULL b2 = pack2(bj, bj);
#pragma unroll
        for (int rp = 0; rp < 4; rp++) acc[c][rp] = b2;
    }

    const float* abase = As + ry * 8;
    const float* bbase = Bs + cx * 4;

    // software pipeline: prefetch k+1 while computing k (prefetch of k=K lands in pad rows)
    ulonglong2 a01 = *(const ulonglong2*)(abase);
    ulonglong2 a23 = *(const ulonglong2*)(abase + 4);
    float4     b4  = *(const float4*)(bbase);
#pragma unroll 4
    for (int k = 0; k < K; k++) {
        ulonglong2 a01c = a01, a23c = a23;
        float4     b4c  = b4;
        a01 = *(const ulonglong2*)(abase + (k + 1) * MP);
        a23 = *(const ulonglong2*)(abase + (k + 1) * MP + 4);
        b4  = *(const float4*)(bbase + (k + 1) * BP);
#pragma unroll
        for (int c = 0; c < 4; c++) {
            float bc = (c == 0) ? b4c.x : (c == 1) ? b4c.y : (c == 2) ? b4c.z : b4c.w;
            ULL w2 = pack2(bc, bc);
            fma2(acc[c][0], a01c.x, w2);
            fma2(acc[c][1], a01c.y, w2);
            fma2(acc[c][2], a23c.x, w2);
            fma2(acc[c][3], a23c.y, w2);
        }
    }

    if (j0 + cx * 4 < 300) {
        float v[4][8];
#pragma unroll
        for (int c = 0; c < 4; c++)
#pragma unroll
            for (int rp = 0; rp < 4; rp++)
                unpack2(acc[c][rp], v[c][2 * rp], v[c][2 * rp + 1]);
#pragma unroll
        for (int r = 0; r < 8; r++) {
            float4 f;
            f.x = v[0][r]; f.y = v[1][r]; f.z = v[2][r]; f.w = v[3][r];
            *(float4*)(gi + (n0 + ry * 8 + r) * 300 + j0 + cx * 4) = f;
        }
    }
}

// ---------------- persistent GRU recurrence ----------------
// 128 blocks x 8 batch rows; 608 threads (600 active): thread = (j, rh), rows rh*4..rh*4+3.
// BITWISE round-4 semantics: f32x2 lanes = row pairs, each row's chain is k-ascending from 0.
// hs layout [k][8]; distance-1 prefetch of (w4, hv[4]) covers LDS latency.
__global__ void __launch_bounds__(608) k_gru(const float* __restrict__ gi,
                                             const float* __restrict__ Whh,
                                             const float* __restrict__ bhh,
                                             const float* __restrict__ h0,
                                             float* __restrict__ y,
                                             float* __restrict__ hfin,
                                             int T) {
    const int WP = 108;   // Ws row stride (k=100..107 zero padding)
    extern __shared__ float sm[];
    float* Ws = sm;                   // [300][108]
    float* hs = sm + 300 * WP;        // [100][8]: hs[k*8 + row]  (+overrun lands in rs)
    float* rs = hs + 800;             // [100][12]: rs[u*12 + rh*4 + r]
    float* zs = rs + 100 * 12;        // [100][12]

    const int tid = threadIdx.x;
    const int b0  = blockIdx.x * 8;
    const bool active = tid < 600;
    const int j  = active ? (tid % 300) : 0;
    const int rh = active ? (tid / 300) : 0;
    const int g  = (j >= 200) ? 2 : (j >= 100) ? 1 : 0;
    const int u  = j - g * 100;

    for (int idx = tid; idx < 300 * WP; idx += 608) {
        int jj = idx / WP, k = idx - jj * WP;
        Ws[idx] = (k < 100) ? Whh[jj * 100 + k] : 0.0f;
    }
    for (int idx = tid; idx < 800; idx += 608) {
        int r = idx & 7, k = idx >> 3;
        hs[idx] = h0 ? h0[(b0 + r) * 100 + k] : 0.0f;
    }
    const float bnn = (active && g == 2) ? bhh[j] : 0.0f;
    const float* wrow = Ws + j * WP;
    const float* hbase = hs + rh * 4;
    __syncthreads();

    for (int t = 0; t < T; t++) {
        float gv[4], an[4], bn[4];
        if (active) {
            const float* gp = gi + ((long)t * 1024 + b0 + rh * 4) * 300 + j;
#pragma unroll
            for (int r = 0; r < 4; r++) gv[r] = gp[r * 300];

            // lanes = row pairs; k-ascending chains. Prefetch next k4 while computing.
            ULL a01 = 0, a23 = 0;
            float4 w4 = *(const float4*)(wrow);
            ulonglong2 hv0 = *(const ulonglong2*)(hbase + 0);
            ulonglong2 hv1 = *(const ulonglong2*)(hbase + 8);
            ulonglong2 hv2 = *(const ulonglong2*)(hbase + 16);
            ulonglong2 hv3 = *(const ulonglong2*)(hbase + 24);
#pragma unroll 5
            for (int k4 = 0; k4 < 25; k4++) {
                float4 w4c = w4;
                ulonglong2 h0c = hv0, h1c = hv1, h2c = hv2, h3c = hv3;
                // prefetch k4+1 (k4=24 reads Ws zero-pad / rs region: in-bounds, unused)
                w4  = *(const float4*)(wrow + (k4 + 1) * 4);
                hv0 = *(const ulonglong2*)(hbase + ((k4 + 1) * 4 + 0) * 8);
                hv1 = *(const ulonglong2*)(hbase + ((k4 + 1) * 4 + 1) * 8);
                hv2 = *(const ulonglong2*)(hbase + ((k4 + 1) * 4 + 2) * 8);
                hv3 = *(const ulonglong2*)(hbase + ((k4 + 1) * 4 + 3) * 8);
                ULL w2;
                w2 = pack2(w4c.x, w4c.x);
                fma2(a01, h0c.x, w2); fma2(a23, h0c.y, w2);
                w2 = pack2(w4c.y, w4c.y);
                fma2(a01, h1c.x, w2); fma2(a23, h1c.y, w2);
                w2 = pack2(w4c.z, w4c.z);
                fma2(a01, h2c.x, w2); fma2(a23, h2c.y, w2);
                w2 = pack2(w4c.w, w4c.w);
                fma2(a01, h3c.x, w2); fma2(a23, h3c.y, w2);
            }
            float ah[4];
            unpack2(a01, ah[0], ah[1]);
            unpack2(a23, ah[2], ah[3]);

            if (g == 0) {
#pragma unroll
                for (int r = 0; r < 4; r++) rs[u * 12 + rh * 4 + r] = sigm(gv[r] + ah[r]);
            } else if (g == 1) {
#pragma unroll
                for (int r = 0; r < 4; r++) zs[u * 12 + rh * 4 + r] = sigm(gv[r] + ah[r]);
            } else {
#pragma unroll
                for (int r = 0; r < 4; r++) { an[r] = gv[r]; bn[r] = ah[r] + bnn; }
            }
        }
        __syncthreads();
        if (active && g == 2) {
            float4 rv = *(const float4*)(rs + u * 12 + rh * 4);
            float4 zv = *(const float4*)(zs + u * 12 + rh * 4);
#pragma unroll
            for (int r = 0; r < 4; r++) {
                float rr = (r == 0) ? rv.x : (r == 1) ? rv.y : (r == 2) ? rv.z : rv.w;
                float zz = (r == 0) ? zv.x : (r == 1) ? zv.y : (r == 2) ? zv.z : zv.w;
                int row = rh * 4 + r;
                float ho = hs[u * 8 + row];
                float nn = tanh_acc(fmaf(rr, bn[r], an[r]));
                float hn = fmaf(zz, ho - nn, nn);
                hs[u * 8 + row] = hn;
                if (y) y[((long)t * 1024 + b0 + row) * 100 + u] = hn;
                if (hfin && t == T - 1) hfin[(b0 + row) * 100 + u] = hn;
            }
        }
        __syncthreads();
    }
}

// ---------------- logits + argmax + target_cal ----------------
__global__ void __launch_bounds__(1024) k_out(float* __restrict__ out,
                                              const float* __restrict__ d1,
                                              const float* __restrict__ W,
                                              const float* __restrict__ b,
                                              const int* __restrict__ tgt) {
    __shared__ float Ws[64 * 101];
    __shared__ float ds[16 * 100];
    __shared__ float ls[16 * 64];
    const int tid = threadIdx.x;

    for (int idx = tid; idx < 64 * 101; idx += 1024) {
        int d = idx / 101, k = idx - d * 101;
        Ws[idx] = (k < 100) ? W[d * 100 + k] : 0.0f;
    }
    const long r0 = (long)blockIdx.x * 16;
    for (int idx = tid; idx < 1600; idx += 1024) {
        int rr = idx / 100, k = idx - rr * 100;
        ds[idx] = d1[(r0 + rr) * 100 + k];
    }
    __syncthreads();

    const int rr = tid >> 6;
    const int d  = tid & 63;
    const float* dp = ds + rr * 100;
    const float* wp = Ws + d * 101;
    float a0 = b[d], a1 = 0.0f;
#pragma unroll 2
    for (int k = 0; k < 100; k += 2) {
        a0 = fmaf(dp[k],     wp[k],     a0);
        a1 = fmaf(dp[k + 1], wp[k + 1], a1);
    }
    float acc = a0 + a1;

    const long row = r0 + rr;
    out[row * 64 + d] = acc;
    ls[rr * 64 + d] = acc;
    __syncthreads();

    if (d == 0) {
        float best = ls[rr * 64];
        int bi = 0;
        for (int k = 1; k < 64; k++) {
            float v = ls[rr * 64 + k];
            if (v > best) { best = v; bi = k; }
        }
        out[5177344 + row] = (float)tgt[row + 1024];
        out[5258240 + row] = (float)bi;
    }
}

// ---------------- launch ----------------
extern "C" void kernel_launch(void* const* d_in, const int* in_sizes, int n_in,
                              void* d_out, int out_size) {
    const float* x     = (const float*)d_in[0];
    const int*   tgt   = (const int*)d_in[1];
    const float* emb   = (const float*)d_in[2];
    const float* eWih0 = (const float*)d_in[3];
    const float* eWhh0 = (const float*)d_in[4];
    const float* ebih0 = (const float*)d_in[5];
    const float* ebhh0 = (const float*)d_in[6];
    const float* eWih1 = (const float*)d_in[7];
    const float* eWhh1 = (const float*)d_in[8];
    const float* ebih1 = (const float*)d_in[9];
    const float* ebhh1 = (const float*)d_in[10];
    const float* dWih0 = (const float*)d_in[11];
    const float* dWhh0 = (const float*)d_in[12];
    const float* dbih0 = (const float*)d_in[13];
    const float* dbhh0 = (const float*)d_in[14];
    const float* dWih1 = (const float*)d_in[15];
    const float* dWhh1 = (const float*)d_in[16];
    const float* dbih1 = (const float*)d_in[17];
    const float* dbhh1 = (const float*)d_in[18];
    const float* linW  = (const float*)d_in[19];
    const float* linb  = (const float*)d_in[20];
    float* out = (float*)d_out;

    float *gi, *buf0, *d1b, *decin, *h0b, *h1b;
    cudaGetSymbolAddress((void**)&gi,    g_gi);
    cudaGetSymbolAddress((void**)&buf0,  g_buf0);
    cudaGetSymbolAddress((void**)&d1b,   g_d1);
    cudaGetSymbolAddress((void**)&decin, g_decin);
    cudaGetSymbolAddress((void**)&h0b,   g_h0);
    cudaGetSymbolAddress((void**)&h1b,   g_h1);

    // +1 padding row on As and Bs for unconditional k+1 prefetch
    const int SMEM_G26  = ((26 + 1) * 132 + (26 + 1) * 68) * 4;     // 21,600 B
    const int SMEM_G100 = ((100 + 1) * 132 + (100 + 1) * 68) * 4;   // 80,800 B
    const int SMEM_GRU  = (300 * 108 + 800 + 2 * 1200) * 4;         // 142,400 B
    cudaFuncSetAttribute((const void*)k_gemm<26>,
                         cudaFuncAttributeMaxDynamicSharedMemorySize, SMEM_G26);
    cudaFuncSetAttribute((const void*)k_gemm<100>,
                         cudaFuncAttributeMaxDynamicSharedMemorySize, SMEM_G100);
    cudaFuncSetAttribute((const void*)k_gru,
                         cudaFuncAttributeMaxDynamicSharedMemorySize, SMEM_GRU);

    // decoder input embedding
    k_embed<<<(80 * 1024 * 26 + 255) / 256, 256>>>(tgt, emb, decin);

    // encoder layer 0
    k_gemm<26><<<dim3(4000, 5), 256, SMEM_G26>>>(gi, x, eWih0, ebih0, ebhh0);
    k_gru<<<128, 608, SMEM_GRU>>>(gi, eWhh0, ebhh0, nullptr, buf0, h0b, 500);

    // encoder layer 1 (only final hidden needed)
    k_gemm<100><<<dim3(4000, 5), 256, SMEM_G100>>>(gi, buf0, eWih1, ebih1, ebhh1);
    k_gru<<<128, 608, SMEM_GRU>>>(gi, eWhh1, ebhh1, nullptr, nullptr, h1b, 500);

    // decoder layer 0
    k_gemm<26><<<dim3(640, 5), 256, SMEM_G26>>>(gi, decin, dWih0, dbih0, dbhh0);
    k_gru<<<128, 608, SMEM_GRU>>>(gi, dWhh0, dbhh0, h0b, buf0, nullptr, 80);

    // decoder layer 1
    k_gemm<100><<<dim3(640, 5), 256, SMEM_G100>>>(gi, buf0, dWih1, dbih1, dbhh1);
    k_gru<<<128, 608, SMEM_GRU>>>(gi, dWhh1, dbhh1, h1b, d1b, nullptr, 80);

    // logits + outputs
    k_out<<<5056, 1024>>>(out, d1b, linW, linb, tgt);
}

// round 8
// speedup vs baseline: 1.0134x; 1.0134x over previous
#include <cuda_runtime.h>

typedef unsigned long long ULL;

// ---------------- scratch (static device globals; no allocation) ----------------
static __device__ float g_gi[500 * 1024 * 300];     // 614.4 MB: gi for current layer
static __device__ float g_buf0[500 * 1024 * 100];   // 204.8 MB: e0 / d0 sequence
static __device__ float g_d1[80 * 1024 * 100];      // decoder layer-1 outputs
static __device__ float g_decin[80 * 1024 * 26];    // embedded decoder inputs
static __device__ float g_h0[1024 * 100];           // h_enc0
static __device__ float g_h1[1024 * 100];           // h_enc1

// ---------------- f32x2 helpers ----------------
__device__ __forceinline__ ULL pack2(float lo, float hi) {
    ULL r;
    asm("mov.b64 %0, {%1, %2};" : "=l"(r) : "f"(lo), "f"(hi));
    return r;
}
__device__ __forceinline__ void unpack2(ULL v, float& lo, float& hi) {
    asm("mov.b64 {%0, %1}, %2;" : "=f"(lo), "=f"(hi) : "l"(v));
}
__device__ __forceinline__ void fma2(ULL& d, ULL a, ULL b) {
    asm("fma.rn.f32x2 %0, %1, %2, %0;" : "+l"(d) : "l"(a), "l"(b));
}

// ---------------- accurate activations (immune to fast-math flags) ----------------
__device__ __forceinline__ float exp_acc(float x) {
    float z = x * 1.4426950408889634f;
    float n = rintf(z);
    float r = fmaf(n, -0.693147182464599609375f, x);
    r = fmaf(n, 1.9046542121259336e-9f, r);
    float p = 1.9841270114e-4f;
    p = fmaf(p, r, 1.3888888877e-3f);
    p = fmaf(p, r, 8.3333337680e-3f);
    p = fmaf(p, r, 4.1666667908e-2f);
    p = fmaf(p, r, 1.6666667163e-1f);
    p = fmaf(p, r, 0.5f);
    p = fmaf(p, r, 1.0f);
    p = fmaf(p, r, 1.0f);
    int i = (int)n;
    float sc = __int_as_float((i + 127) << 23);
    return p * sc;
}
__device__ __forceinline__ float sigm(float x) {
    float xc = fminf(fmaxf(x, -30.0f), 30.0f);
    float s = exp_acc(-xc);
    return __fdiv_rn(1.0f, 1.0f + s);
}
__device__ __forceinline__ float tanh_acc(float x) {
    float ax = fabsf(x);
    float t;
    if (ax < 0.25f) {
        float x2 = x * x;
        float p = 0.021869488536155203f;
        p = fmaf(p, x2, -0.05396825396825397f);
        p = fmaf(p, x2, 0.13333333333333333f);
        p = fmaf(p, x2, -0.3333333333333333f);
        p = fmaf(p, x2, 1.0f);
        t = x * p;
    } else {
        float a = fminf(ax, 9.0f);
        float s = exp_acc(-2.0f * a);
        t = __fdiv_rn(1.0f - s, 1.0f + s);
        t = copysignf(t, x);
    }
    return t;
}

// ---------------- embedding gather ----------------
__global__ void k_embed(const int* __restrict__ tgt,
                        const float* __restrict__ emb,
                        float* __restrict__ out) {
    int idx = blockIdx.x * blockDim.x + threadIdx.x;
    const int total = 80 * 1024 * 26;
    if (idx < total) {
        int e  = idx % 26;
        int pb = idx / 26;
        int t = tgt[pb] & 63;
        out[idx] = emb[t * 26 + e];
    }
}

// ---------------- gi GEMM (2D register tile + distance-1 smem prefetch) ----------------
template <int K>
__global__ void __launch_bounds__(256) k_gemm(float* __restrict__ gi,
                                              const float* __restrict__ x,
                                              const float* __restrict__ W,
                                              const float* __restrict__ bih,
                                              const float* __restrict__ bhh) {
    const int MP = 132;
    const int BP = 68;
    extern __shared__ float sm[];
    float* As = sm;                  // [K+1][132]
    float* Bs = sm + (K + 1) * MP;   // [K+1][68]

    const int tid = threadIdx.x;
    const long n0 = (long)blockIdx.x * 128;
    const int  j0 = blockIdx.y * 64;

    for (int idx = tid; idx < 128 * K; idx += 256) {
        int m = idx / K, k = idx - m * K;
        As[k * MP + m] = x[(n0 + m) * K + k];
    }
    for (int idx = tid; idx < 64 * K; idx += 256) {
        int jj = idx / K, k = idx - jj * K;
        int j = j0 + jj;
        Bs[k * BP + jj] = (j < 300) ? W[j * K + k] : 0.0f;
    }
    __syncthreads();

    const int cx = tid & 15;
    const int ry = tid >> 4;

    ULL acc[4][4];
#pragma unroll
    for (int c = 0; c < 4; c++) {
        int j = j0 + cx * 4 + c;
        float bj = 0.0f;
        if (j < 300) bj = bih[j] + ((j < 200) ? bhh[j] : 0.0f);
        ULL b2 = pack2(bj, bj);
#pragma unroll
        for (int rp = 0; rp < 4; rp++) acc[c][rp] = b2;
    }

    const float* abase = As + ry * 8;
    const float* bbase = Bs + cx * 4;

    ulonglong2 a01 = *(const ulonglong2*)(abase);
    ulonglong2 a23 = *(const ulonglong2*)(abase + 4);
    float4     b4  = *(const float4*)(bbase);
#pragma unroll 4
    for (int k = 0; k < K; k++) {
        ulonglong2 a01c = a01, a23c = a23;
        float4     b4c  = b4;
        a01 = *(const ulonglong2*)(abase + (k + 1) * MP);
        a23 = *(const ulonglong2*)(abase + (k + 1) * MP + 4);
        b4  = *(const float4*)(bbase + (k + 1) * BP);
#pragma unroll
        for (int c = 0; c < 4; c++) {
            float bc = (c == 0) ? b4c.x : (c == 1) ? b4c.y : (c == 2) ? b4c.z : b4c.w;
            ULL w2 = pack2(bc, bc);
            fma2(acc[c][0], a01c.x, w2);
            fma2(acc[c][1], a01c.y, w2);
            fma2(acc[c][2], a23c.x, w2);
            fma2(acc[c][3], a23c.y, w2);
        }
    }

    if (j0 + cx * 4 < 300) {
        float v[4][8];
#pragma unroll
        for (int c = 0; c < 4; c++)
#pragma unroll
            for (int rp = 0; rp < 4; rp++)
                unpack2(acc[c][rp], v[c][2 * rp], v[c][2 * rp + 1]);
#pragma unroll
        for (int r = 0; r < 8; r++) {
            float4 f;
            f.x = v[0][r]; f.y = v[1][r]; f.z = v[2][r]; f.w = v[3][r];
            *(float4*)(gi + (n0 + ry * 8 + r) * 300 + j0 + cx * 4) = f;
        }
    }
}

// ---------------- persistent GRU recurrence (W in registers) ----------------
// 128 blocks x 8 batch rows; 320 threads, 300 active: thread = column j, ALL 8 rows.
// W row lives in 100 registers (staged once). Per k: 2 broadcast LDS.128 + 1 pack + 4 fma2.
// BITWISE round-4 semantics: f32x2 lanes = row pairs, k-ascending chains from 0.
__global__ void __launch_bounds__(320) k_gru(const float* __restrict__ gi,
                                             const float* __restrict__ Whh,
                                             const float* __restrict__ bhh,
                                             const float* __restrict__ h0,
                                             float* __restrict__ y,
                                             float* __restrict__ hfin,
                                             int T) {
    extern __shared__ float sm[];
    float* hs = sm;              // [104][8]: hs[k*8 + row], k>=100 zero pad (prefetch overrun)
    float* rs = sm + 104 * 8;    // [100][8]: rs[u*8 + r]
    float* zs = rs + 800;        // [100][8]
    float* Wst = zs + 800;       // [300*100] staging for Whh

    const int tid = threadIdx.x;
    const int b0  = blockIdx.x * 8;
    const bool active = tid < 300;
    const int j = active ? tid : 0;
    const int g = (j >= 200) ? 2 : (j >= 100) ? 1 : 0;
    const int u = j - g * 100;

    // stage W coalesced, init h
    for (int idx = tid; idx < 30000; idx += 320) Wst[idx] = Whh[idx];
    for (int idx = tid; idx < 832; idx += 320) {
        int r = idx & 7, k = idx >> 3;
        hs[idx] = (k < 100 && h0) ? h0[(b0 + r) * 100 + k] : 0.0f;
    }
    __syncthreads();

    // W row -> registers
    float wreg[100];
#pragma unroll
    for (int k = 0; k < 100; k++) wreg[k] = Wst[j * 100 + k];

    const float bnn = (active && g == 2) ? bhh[j] : 0.0f;
    __syncthreads();

    for (int t = 0; t < T; t++) {
        float gv[8], an[8], bnl[8];
        if (active) {
            const float* gp = gi + ((long)t * 1024 + b0) * 300 + j;
#pragma unroll
            for (int r = 0; r < 8; r++) gv[r] = gp[r * 300];

            // matvec: lanes = row pairs, k-ascending chains; depth-2 h prefetch
            ULL a01 = 0, a23 = 0, a45 = 0, a67 = 0;
            ulonglong2 p0a = *(const ulonglong2*)(hs + 0);
            ulonglong2 p0b = *(const ulonglong2*)(hs + 4);
            ulonglong2 p1a = *(const ulonglong2*)(hs + 8);
            ulonglong2 p1b = *(const ulonglong2*)(hs + 12);
#pragma unroll
            for (int k = 0; k < 100; k += 2) {
                ulonglong2 c0a = p0a, c0b = p0b, c1a = p1a, c1b = p1b;
                p0a = *(const ulonglong2*)(hs + (k + 2) * 8);
                p0b = *(const ulonglong2*)(hs + (k + 2) * 8 + 4);
                p1a = *(const ulonglong2*)(hs + (k + 3) * 8);
                p1b = *(const ulonglong2*)(hs + (k + 3) * 8 + 4);
                ULL w2 = pack2(wreg[k], wreg[k]);
                fma2(a01, c0a.x, w2); fma2(a23, c0a.y, w2);
                fma2(a45, c0b.x, w2); fma2(a67, c0b.y, w2);
                w2 = pack2(wreg[k + 1], wreg[k + 1]);
                fma2(a01, c1a.x, w2); fma2(a23, c1a.y, w2);
                fma2(a45, c1b.x, w2); fma2(a67, c1b.y, w2);
            }
            float ah[8];
            unpack2(a01, ah[0], ah[1]);
            unpack2(a23, ah[2], ah[3]);
            unpack2(a45, ah[4], ah[5]);
            unpack2(a67, ah[6], ah[7]);

            if (g == 0) {
                float v[8];
#pragma unroll
                for (int r = 0; r < 8; r++) v[r] = sigm(gv[r] + ah[r]);
                *(float4*)(rs + u * 8)     = make_float4(v[0], v[1], v[2], v[3]);
                *(float4*)(rs + u * 8 + 4) = make_float4(v[4], v[5], v[6], v[7]);
            } else if (g == 1) {
                float v[8];
#pragma unroll
                for (int r = 0; r < 8; r++) v[r] = sigm(gv[r] + ah[r]);
                *(float4*)(zs + u * 8)     = make_float4(v[0], v[1], v[2], v[3]);
                *(float4*)(zs + u * 8 + 4) = make_float4(v[4], v[5], v[6], v[7]);
            } else {
#pragma unroll
                for (int r = 0; r < 8; r++) { an[r] = gv[r]; bnl[r] = ah[r] + bnn; }
            }
        }
        __syncthreads();
        if (active && g == 2) {
            float4 rv0 = *(const float4*)(rs + u * 8);
            float4 rv1 = *(const float4*)(rs + u * 8 + 4);
            float4 zv0 = *(const float4*)(zs + u * 8);
            float4 zv1 = *(const float4*)(zs + u * 8 + 4);
            float4 ho0 = *(const float4*)(hs + u * 8);
            float4 ho1 = *(const float4*)(hs + u * 8 + 4);
            float rrv[8] = {rv0.x, rv0.y, rv0.z, rv0.w, rv1.x, rv1.y, rv1.z, rv1.w};
            float zzv[8] = {zv0.x, zv0.y, zv0.z, zv0.w, zv1.x, zv1.y, zv1.z, zv1.w};
            float hov[8] = {ho0.x, ho0.y, ho0.z, ho0.w, ho1.x, ho1.y, ho1.z, ho1.w};
            float hn[8];
#pragma unroll
            for (int r = 0; r < 8; r++) {
                float nn = tanh_acc(fmaf(rrv[r], bnl[r], an[r]));
                hn[r] = fmaf(zzv[r], hov[r] - nn, nn);
            }
            *(float4*)(hs + u * 8)     = make_float4(hn[0], hn[1], hn[2], hn[3]);
            *(float4*)(hs + u * 8 + 4) = make_float4(hn[4], hn[5], hn[6], hn[7]);
            if (y) {
                float* yp = y + ((long)t * 1024 + b0) * 100 + u;
#pragma unroll
                for (int r = 0; r < 8; r++) yp[r * 100] = hn[r];
            }
            if (hfin && t == T - 1) {
#pragma unroll
                for (int r = 0; r < 8; r++) hfin[(b0 + r) * 100 + u] = hn[r];
            }
        }
        __syncthreads();
    }
}

// ---------------- logits + argmax + target_cal ----------------
__global__ void __launch_bounds__(1024) k_out(float* __restrict__ out,
                                              const float* __restrict__ d1,
                                              const float* __restrict__ W,
                                              const float* __restrict__ b,
                                              const int* __restrict__ tgt) {
    __shared__ float Ws[64 * 101];
    __shared__ float ds[16 * 100];
    __shared__ float ls[16 * 64];
    const int tid = threadIdx.x;

    for (int idx = tid; idx < 64 * 101; idx += 1024) {
        int d = idx / 101, k = idx - d * 101;
        Ws[idx] = (k < 100) ? W[d * 100 + k] : 0.0f;
    }
    const long r0 = (long)blockIdx.x * 16;
    for (int idx = tid; idx < 1600; idx += 1024) {
        int rr = idx / 100, k = idx - rr * 100;
        ds[idx] = d1[(r0 + rr) * 100 + k];
    }
    __syncthreads();

    const int rr = tid >> 6;
    const int d  = tid & 63;
    const float* dp = ds + rr * 100;
    const float* wp = Ws + d * 101;
    float a0 = b[d], a1 = 0.0f;
#pragma unroll 2
    for (int k = 0; k < 100; k += 2) {
        a0 = fmaf(dp[k],     wp[k],     a0);
        a1 = fmaf(dp[k + 1], wp[k + 1], a1);
    }
    float acc = a0 + a1;

    const long row = r0 + rr;
    out[row * 64 + d] = acc;
    ls[rr * 64 + d] = acc;
    __syncthreads();

    if (d == 0) {
        float best = ls[rr * 64];
        int bi = 0;
        for (int k = 1; k < 64; k++) {
            float v = ls[rr * 64 + k];
            if (v > best) { best = v; bi = k; }
        }
        out[5177344 + row] = (float)tgt[row + 1024];
        out[5258240 + row] = (float)bi;
    }
}

// ---------------- launch ----------------
extern "C" void kernel_launch(void* const* d_in, const int* in_sizes, int n_in,
                              void* d_out, int out_size) {
    const float* x     = (const float*)d_in[0];
    const int*   tgt   = (const int*)d_in[1];
    const float* emb   = (const float*)d_in[2];
    const float* eWih0 = (const float*)d_in[3];
    const float* eWhh0 = (const float*)d_in[4];
    const float* ebih0 = (const float*)d_in[5];
    const float* ebhh0 = (const float*)d_in[6];
    const float* eWih1 = (const float*)d_in[7];
    const float* eWhh1 = (const float*)d_in[8];
    const float* ebih1 = (const float*)d_in[9];
    const float* ebhh1 = (const float*)d_in[10];
    const float* dWih0 = (const float*)d_in[11];
    const float* dWhh0 = (const float*)d_in[12];
    const float* dbih0 = (const float*)d_in[13];
    const float* dbhh0 = (const float*)d_in[14];
    const float* dWih1 = (const float*)d_in[15];
    const float* dWhh1 = (const float*)d_in[16];
    const float* dbih1 = (const float*)d_in[17];
    const float* dbhh1 = (const float*)d_in[18];
    const float* linW  = (const float*)d_in[19];
    const float* linb  = (const float*)d_in[20];
    float* out = (float*)d_out;

    float *gi, *buf0, *d1b, *decin, *h0b, *h1b;
    cudaGetSymbolAddress((void**)&gi,    g_gi);
    cudaGetSymbolAddress((void**)&buf0,  g_buf0);
    cudaGetSymbolAddress((void**)&d1b,   g_d1);
    cudaGetSymbolAddress((void**)&decin, g_decin);
    cudaGetSymbolAddress((void**)&h0b,   g_h0);
    cudaGetSymbolAddress((void**)&h1b,   g_h1);

    const int SMEM_G26  = ((26 + 1) * 132 + (26 + 1) * 68) * 4;     // 21,600 B
    const int SMEM_G100 = ((100 + 1) * 132 + (100 + 1) * 68) * 4;   // 80,800 B
    const int SMEM_GRU  = (104 * 8 + 2 * 800 + 300 * 100) * 4;      // 129,728 B
    cudaFuncSetAttribute((const void*)k_gemm<26>,
                         cudaFuncAttributeMaxDynamicSharedMemorySize, SMEM_G26);
    cudaFuncSetAttribute((const void*)k_gemm<100>,
                         cudaFuncAttributeMaxDynamicSharedMemorySize, SMEM_G100);
    cudaFuncSetAttribute((const void*)k_gru,
                         cudaFuncAttributeMaxDynamicSharedMemorySize, SMEM_GRU);

    // decoder input embedding
    k_embed<<<(80 * 1024 * 26 + 255) / 256, 256>>>(tgt, emb, decin);

    // encoder layer 0
    k_gemm<26><<<dim3(4000, 5), 256, SMEM_G26>>>(gi, x, eWih0, ebih0, ebhh0);
    k_gru<<<128, 320, SMEM_GRU>>>(gi, eWhh0, ebhh0, nullptr, buf0, h0b, 500);

    // encoder layer 1 (only final hidden needed)
    k_gemm<100><<<dim3(4000, 5), 256, SMEM_G100>>>(gi, buf0, eWih1, ebih1, ebhh1);
    k_gru<<<128, 320, SMEM_GRU>>>(gi, eWhh1, ebhh1, nullptr, nullptr, h1b, 500);

    // decoder layer 0
    k_gemm<26><<<dim3(640, 5), 256, SMEM_G26>>>(gi, decin, dWih0, dbih0, dbhh0);
    k_gru<<<128, 320, SMEM_GRU>>>(gi, dWhh0, dbhh0, h0b, buf0, nullptr, 80);

    // decoder layer 1
    k_gemm<100><<<dim3(640, 5), 256, SMEM_G100>>>(gi, buf0, dWih1, dbih1, dbhh1);
    k_gru<<<128, 320, SMEM_GRU>>>(gi, dWhh1, dbhh1, h1b, d1b, nullptr, 80);

    // logits + outputs
    k_out<<<5056, 1024>>>(out, d1b, linW, linb, tgt);
}

// round 9
// speedup vs baseline: 1.1373x; 1.1222x over previous
#include <cuda_runtime.h>

typedef unsigned long long ULL;

// ---------------- scratch (static device globals; no allocation) ----------------
static __device__ float g_gi[500 * 1024 * 300];     // 614.4 MB: encoder gi
static __device__ float g_gid[80 * 1024 * 300];     // 98.3 MB: decoder gi (both layers)
static __device__ float g_buf0[500 * 1024 * 100];   // 204.8 MB: encoder e0 sequence
static __device__ float g_bufd[80 * 1024 * 100];    // decoder d0 sequence
static __device__ float g_d1[80 * 1024 * 100];      // decoder layer-1 outputs
static __device__ float g_decin[80 * 1024 * 26];    // embedded decoder inputs
static __device__ float g_h0[1024 * 100];           // h_enc0
static __device__ float g_h1[1024 * 100];           // h_enc1

// ---------------- f32x2 helpers ----------------
__device__ __forceinline__ ULL pack2(float lo, float hi) {
    ULL r;
    asm("mov.b64 %0, {%1, %2};" : "=l"(r) : "f"(lo), "f"(hi));
    return r;
}
__device__ __forceinline__ void unpack2(ULL v, float& lo, float& hi) {
    asm("mov.b64 {%0, %1}, %2;" : "=f"(lo), "=f"(hi) : "l"(v));
}
__device__ __forceinline__ void fma2(ULL& d, ULL a, ULL b) {
    asm("fma.rn.f32x2 %0, %1, %2, %0;" : "+l"(d) : "l"(a), "l"(b));
}

// ---------------- accurate activations (immune to fast-math flags) ----------------
__device__ __forceinline__ float exp_acc(float x) {
    float z = x * 1.4426950408889634f;
    float n = rintf(z);
    float r = fmaf(n, -0.693147182464599609375f, x);
    r = fmaf(n, 1.9046542121259336e-9f, r);
    float p = 1.9841270114e-4f;
    p = fmaf(p, r, 1.3888888877e-3f);
    p = fmaf(p, r, 8.3333337680e-3f);
    p = fmaf(p, r, 4.1666667908e-2f);
    p = fmaf(p, r, 1.6666667163e-1f);
    p = fmaf(p, r, 0.5f);
    p = fmaf(p, r, 1.0f);
    p = fmaf(p, r, 1.0f);
    int i = (int)n;
    float sc = __int_as_float((i + 127) << 23);
    return p * sc;
}
__device__ __forceinline__ float sigm(float x) {
    float xc = fminf(fmaxf(x, -30.0f), 30.0f);
    float s = exp_acc(-xc);
    return __fdiv_rn(1.0f, 1.0f + s);
}
__device__ __forceinline__ float tanh_acc(float x) {
    float ax = fabsf(x);
    float t;
    if (ax < 0.25f) {
        float x2 = x * x;
        float p = 0.021869488536155203f;
        p = fmaf(p, x2, -0.05396825396825397f);
        p = fmaf(p, x2, 0.13333333333333333f);
        p = fmaf(p, x2, -0.3333333333333333f);
        p = fmaf(p, x2, 1.0f);
        t = x * p;
    } else {
        float a = fminf(ax, 9.0f);
        float s = exp_acc(-2.0f * a);
        t = __fdiv_rn(1.0f - s, 1.0f + s);
        t = copysignf(t, x);
    }
    return t;
}

// ---------------- embedding gather ----------------
__global__ void k_embed(const int* __restrict__ tgt,
                        const float* __restrict__ emb,
                        float* __restrict__ out) {
    int idx = blockIdx.x * blockDim.x + threadIdx.x;
    const int total = 80 * 1024 * 26;
    if (idx < total) {
        int e  = idx % 26;
        int pb = idx / 26;
        int t = tgt[pb] & 63;
        out[idx] = emb[t * 26 + e];
    }
}

// ---------------- gi GEMM (2D register tile + distance-1 smem prefetch) ----------------
template <int K>
__global__ void __launch_bounds__(256) k_gemm(float* __restrict__ gi,
                                              const float* __restrict__ x,
                                              const float* __restrict__ W,
                                              const float* __restrict__ bih,
                                              const float* __restrict__ bhh) {
    const int MP = 132;
    const int BP = 68;
    extern __shared__ float sm[];
    float* As = sm;                  // [K+1][132]
    float* Bs = sm + (K + 1) * MP;   // [K+1][68]

    const int tid = threadIdx.x;
    const long n0 = (long)blockIdx.x * 128;
    const int  j0 = blockIdx.y * 64;

    for (int idx = tid; idx < 128 * K; idx += 256) {
        int m = idx / K, k = idx - m * K;
        As[k * MP + m] = x[(n0 + m) * K + k];
    }
    for (int idx = tid; idx < 64 * K; idx += 256) {
        int jj = idx / K, k = idx - jj * K;
        int j = j0 + jj;
        Bs[k * BP + jj] = (j < 300) ? W[j * K + k] : 0.0f;
    }
    __syncthreads();

    const int cx = tid & 15;
    const int ry = tid >> 4;

    ULL acc[4][4];
#pragma unroll
    for (int c = 0; c < 4; c++) {
        int j = j0 + cx * 4 + c;
        float bj = 0.0f;
        if (j < 300) bj = bih[j] + ((j < 200) ? bhh[j] : 0.0f);
        ULL b2 = pack2(bj, bj);
#pragma unroll
        for (int rp = 0; rp < 4; rp++) acc[c][rp] = b2;
    }

    const float* abase = As + ry * 8;
    const float* bbase = Bs + cx * 4;

    ulonglong2 a01 = *(const ulonglong2*)(abase);
    ulonglong2 a23 = *(const ulonglong2*)(abase + 4);
    float4     b4  = *(const float4*)(bbase);
#pragma unroll 4
    for (int k = 0; k < K; k++) {
        ulonglong2 a01c = a01, a23c = a23;
        float4     b4c  = b4;
        a01 = *(const ulonglong2*)(abase + (k + 1) * MP);
        a23 = *(const ulonglong2*)(abase + (k + 1) * MP + 4);
        b4  = *(const float4*)(bbase + (k + 1) * BP);
#pragma unroll
        for (int c = 0; c < 4; c++) {
            float bc = (c == 0) ? b4c.x : (c == 1) ? b4c.y : (c == 2) ? b4c.z : b4c.w;
            ULL w2 = pack2(bc, bc);
            fma2(acc[c][0], a01c.x, w2);
            fma2(acc[c][1], a01c.y, w2);
            fma2(acc[c][2], a23c.x, w2);
            fma2(acc[c][3], a23c.y, w2);
        }
    }

    if (j0 + cx * 4 < 300) {
        float v[4][8];
#pragma unroll
        for (int c = 0; c < 4; c++)
#pragma unroll
            for (int rp = 0; rp < 4; rp++)
                unpack2(acc[c][rp], v[c][2 * rp], v[c][2 * rp + 1]);
#pragma unroll
        for (int r = 0; r < 8; r++) {
            float4 f;
            f.x = v[0][r]; f.y = v[1][r]; f.z = v[2][r]; f.w = v[3][r];
            *(float4*)(gi + (n0 + ry * 8 + r) * 300 + j0 + cx * 4) = f;
        }
    }
}

// ---------------- persistent GRU recurrence (W in registers, small smem) ----------------
// 128 blocks x 8 batch rows; 320 threads, 300 active: thread = column j, ALL 8 rows.
// BITWISE round-4 semantics: f32x2 lanes = row pairs, k-ascending chains from 0.
// Phase B (tanh/update) distributed over all 300 threads via as_/bs_ smem relay.
__global__ void __launch_bounds__(320) k_gru(const float* __restrict__ gi,
                                             const float* __restrict__ Whh,
                                             const float* __restrict__ bhh,
                                             const float* __restrict__ h0,
                                             float* __restrict__ y,
                                             float* __restrict__ hfin,
                                             int T) {
    __shared__ float hs[104 * 8];   // [k][8], k>=100 zero pad (prefetch overrun)
    __shared__ float rs[800];       // [u][8]
    __shared__ float zs[800];
    __shared__ float as_[800];      // raw n-gate input  (gv)
    __shared__ float bs_[800];      // raw n-gate hidden (ah + bhh_n)

    const int tid = threadIdx.x;
    const int b0  = blockIdx.x * 8;
    const bool active = tid < 300;
    const int j = active ? tid : 0;
    const int g = (j >= 200) ? 2 : (j >= 100) ? 1 : 0;
    const int u = j - g * 100;

    for (int idx = tid; idx < 832; idx += 320) {
        int r = idx & 7, k = idx >> 3;
        hs[idx] = (k < 100 && h0) ? h0[(b0 + r) * 100 + k] : 0.0f;
    }

    // W row -> registers (Whh + j*100 is 400j bytes -> 16B aligned)
    float wreg[100];
    {
        const float4* wp = (const float4*)(Whh + j * 100);
#pragma unroll
        for (int k4 = 0; k4 < 25; k4++) {
            float4 w = wp[k4];
            wreg[k4 * 4 + 0] = w.x;
            wreg[k4 * 4 + 1] = w.y;
            wreg[k4 * 4 + 2] = w.z;
            wreg[k4 * 4 + 3] = w.w;
        }
    }
    const float bnn = (active && g == 2) ? bhh[j] : 0.0f;
    __syncthreads();

    for (int t = 0; t < T; t++) {
        if (active) {
            float gv[8];
            const float* gp = gi + ((long)t * 1024 + b0) * 300 + j;
#pragma unroll
            for (int r = 0; r < 8; r++) gv[r] = gp[r * 300];

            // matvec: lanes = row pairs, k-ascending chains; depth-2 h prefetch
            ULL a01 = 0, a23 = 0, a45 = 0, a67 = 0;
            ulonglong2 p0a = *(const ulonglong2*)(hs + 0);
            ulonglong2 p0b = *(const ulonglong2*)(hs + 4);
            ulonglong2 p1a = *(const ulonglong2*)(hs + 8);
            ulonglong2 p1b = *(const ulonglong2*)(hs + 12);
#pragma unroll
            for (int k = 0; k < 100; k += 2) {
                ulonglong2 c0a = p0a, c0b = p0b, c1a = p1a, c1b = p1b;
                p0a = *(const ulonglong2*)(hs + (k + 2) * 8);
                p0b = *(const ulonglong2*)(hs + (k + 2) * 8 + 4);
                p1a = *(const ulonglong2*)(hs + (k + 3) * 8);
                p1b = *(const ulonglong2*)(hs + (k + 3) * 8 + 4);
                ULL w2 = pack2(wreg[k], wreg[k]);
                fma2(a01, c0a.x, w2); fma2(a23, c0a.y, w2);
                fma2(a45, c0b.x, w2); fma2(a67, c0b.y, w2);
                w2 = pack2(wreg[k + 1], wreg[k + 1]);
                fma2(a01, c1a.x, w2); fma2(a23, c1a.y, w2);
                fma2(a45, c1b.x, w2); fma2(a67, c1b.y, w2);
            }
            float ah[8];
            unpack2(a01, ah[0], ah[1]);
            unpack2(a23, ah[2], ah[3]);
            unpack2(a45, ah[4], ah[5]);
            unpack2(a67, ah[6], ah[7]);

            if (g == 0) {
                float v[8];
#pragma unroll
                for (int r = 0; r < 8; r++) v[r] = sigm(gv[r] + ah[r]);
                *(float4*)(rs + u * 8)     = make_float4(v[0], v[1], v[2], v[3]);
                *(float4*)(rs + u * 8 + 4) = make_float4(v[4], v[5], v[6], v[7]);
            } else if (g == 1) {
                float v[8];
#pragma unroll
                for (int r = 0; r < 8; r++) v[r] = sigm(gv[r] + ah[r]);
                *(float4*)(zs + u * 8)     = make_float4(v[0], v[1], v[2], v[3]);
                *(float4*)(zs + u * 8 + 4) = make_float4(v[4], v[5], v[6], v[7]);
            } else {
                float bv[8];
#pragma unroll
                for (int r = 0; r < 8; r++) bv[r] = ah[r] + bnn;
                *(float4*)(as_ + u * 8)     = make_float4(gv[0], gv[1], gv[2], gv[3]);
                *(float4*)(as_ + u * 8 + 4) = make_float4(gv[4], gv[5], gv[6], gv[7]);
                *(float4*)(bs_ + u * 8)     = make_float4(bv[0], bv[1], bv[2], bv[3]);
                *(float4*)(bs_ + u * 8 + 4) = make_float4(bv[4], bv[5], bv[6], bv[7]);
            }
        }
        __syncthreads();
        // Phase B: all 300 threads update cells (u,r); same ops/values as before -> bitwise
        if (active) {
#pragma unroll
            for (int c = tid; c < 800; c += 300) {
                int uu = c >> 3, rr_ = c & 7;
                float rr = rs[c];
                float zz = zs[c];
                float av = as_[c];
                float bv = bs_[c];
                float ho = hs[c];
                float nn = tanh_acc(fmaf(rr, bv, av));
                float hn = fmaf(zz, ho - nn, nn);
                hs[c] = hn;
                if (y) y[((long)t * 1024 + b0 + rr_) * 100 + uu] = hn;
                if (hfin && t == T - 1) hfin[(b0 + rr_) * 100 + uu] = hn;
            }
        }
        __syncthreads();
    }
}

// ---------------- logits + argmax + target_cal ----------------
__global__ void __launch_bounds__(1024) k_out(float* __restrict__ out,
                                              const float* __restrict__ d1,
                                              const float* __restrict__ W,
                                              const float* __restrict__ b,
                                              const int* __restrict__ tgt) {
    __shared__ float Ws[64 * 101];
    __shared__ float ds[16 * 100];
    __shared__ float ls[16 * 64];
    const int tid = threadIdx.x;

    for (int idx = tid; idx < 64 * 101; idx += 1024) {
        int d = idx / 101, k = idx - d * 101;
        Ws[idx] = (k < 100) ? W[d * 100 + k] : 0.0f;
    }
    const long r0 = (long)blockIdx.x * 16;
    for (int idx = tid; idx < 1600; idx += 1024) {
        int rr = idx / 100, k = idx - rr * 100;
        ds[idx] = d1[(r0 + rr) * 100 + k];
    }
    __syncthreads();

    const int rr = tid >> 6;
    const int d  = tid & 63;
    const float* dp = ds + rr * 100;
    const float* wp = Ws + d * 101;
    float a0 = b[d], a1 = 0.0f;
#pragma unroll 2
    for (int k = 0; k < 100; k += 2) {
        a0 = fmaf(dp[k],     wp[k],     a0);
        a1 = fmaf(dp[k + 1], wp[k + 1], a1);
    }
    float acc = a0 + a1;

    const long row = r0 + rr;
    out[row * 64 + d] = acc;
    ls[rr * 64 + d] = acc;
    __syncthreads();

    if (d == 0) {
        float best = ls[rr * 64];
        int bi = 0;
        for (int k = 1; k < 64; k++) {
            float v = ls[rr * 64 + k];
            if (v > best) { best = v; bi = k; }
        }
        out[5177344 + row] = (float)tgt[row + 1024];
        out[5258240 + row] = (float)bi;
    }
}

// ---------------- launch ----------------
extern "C" void kernel_launch(void* const* d_in, const int* in_sizes, int n_in,
                              void* d_out, int out_size) {
    const float* x     = (const float*)d_in[0];
    const int*   tgt   = (const int*)d_in[1];
    const float* emb   = (const float*)d_in[2];
    const float* eWih0 = (const float*)d_in[3];
    const float* eWhh0 = (const float*)d_in[4];
    const float* ebih0 = (const float*)d_in[5];
    const float* ebhh0 = (const float*)d_in[6];
    const float* eWih1 = (const float*)d_in[7];
    const float* eWhh1 = (const float*)d_in[8];
    const float* ebih1 = (const float*)d_in[9];
    const float* ebhh1 = (const float*)d_in[10];
    const float* dWih0 = (const float*)d_in[11];
    const float* dWhh0 = (const float*)d_in[12];
    const float* dbih0 = (const float*)d_in[13];
    const float* dbhh0 = (const float*)d_in[14];
    const float* dWih1 = (const float*)d_in[15];
    const float* dWhh1 = (const float*)d_in[16];
    const float* dbih1 = (const float*)d_in[17];
    const float* dbhh1 = (const float*)d_in[18];
    const float* linW  = (const float*)d_in[19];
    const float* linb  = (const float*)d_in[20];
    float* out = (float*)d_out;

    float *gi, *gid, *buf0, *bufd, *d1b, *decin, *h0b, *h1b;
    cudaGetSymbolAddress((void**)&gi,    g_gi);
    cudaGetSymbolAddress((void**)&gid,   g_gid);
    cudaGetSymbolAddress((void**)&buf0,  g_buf0);
    cudaGetSymbolAddress((void**)&bufd,  g_bufd);
    cudaGetSymbolAddress((void**)&d1b,   g_d1);
    cudaGetSymbolAddress((void**)&decin, g_decin);
    cudaGetSymbolAddress((void**)&h0b,   g_h0);
    cudaGetSymbolAddress((void**)&h1b,   g_h1);

    // one-time stream/event setup (resource cache only; identical work every call)
    static cudaStream_t s2 = nullptr;
    static cudaEvent_t eF = nullptr, eH0 = nullptr, eH1 = nullptr, eE = nullptr;
    if (!s2) {
        cudaStreamCreateWithFlags(&s2, cudaStreamNonBlocking);
        cudaEventCreateWithFlags(&eF,  cudaEventDisableTiming);
        cudaEventCreateWithFlags(&eH0, cudaEventDisableTiming);
        cudaEventCreateWithFlags(&eH1, cudaEventDisableTiming);
        cudaEventCreateWithFlags(&eE,  cudaEventDisableTiming);
    }

    const int SMEM_G26  = ((26 + 1) * 132 + (26 + 1) * 68) * 4;     // 21,600 B
    const int SMEM_G100 = ((100 + 1) * 132 + (100 + 1) * 68) * 4;   // 80,800 B
    cudaFuncSetAttribute((const void*)k_gemm<26>,
                         cudaFuncAttributeMaxDynamicSharedMemorySize, SMEM_G26);
    cudaFuncSetAttribute((const void*)k_gemm<100>,
                         cudaFuncAttributeMaxDynamicSharedMemorySize, SMEM_G100);

    // ---- fork: decoder-independent prep on s2 ----
    cudaEventRecord(eF, 0);
    cudaStreamWaitEvent(s2, eF, 0);
    k_embed<<<(80 * 1024 * 26 + 255) / 256, 256, 0, s2>>>(tgt, emb, decin);
    k_gemm<26><<<dim3(640, 5), 256, SMEM_G26, s2>>>(gid, decin, dWih0, dbih0, dbhh0);

    // ---- encoder on capture stream ----
    k_gemm<26><<<dim3(4000, 5), 256, SMEM_G26>>>(gi, x, eWih0, ebih0, ebhh0);
    k_gru<<<128, 320>>>(gi, eWhh0, ebhh0, nullptr, buf0, h0b, 500);
    cudaEventRecord(eH0, 0);
    k_gemm<100><<<dim3(4000, 5), 256, SMEM_G100>>>(gi, buf0, eWih1, ebih1, ebhh1);
    k_gru<<<128, 320>>>(gi, eWhh1, ebhh1, nullptr, nullptr, h1b, 500);
    cudaEventRecord(eH1, 0);

    // ---- decoder on s2 (overlaps encoder layer 1) ----
    cudaStreamWaitEvent(s2, eH0, 0);
    k_gru<<<128, 320, 0, s2>>>(gid, dWhh0, dbhh0, h0b, bufd, nullptr, 80);
    k_gemm<100><<<dim3(640, 5), 256, SMEM_G100, s2>>>(gid, bufd, dWih1, dbih1, dbhh1);
    cudaStreamWaitEvent(s2, eH1, 0);
    k_gru<<<128, 320, 0, s2>>>(gid, dWhh1, dbhh1, h1b, d1b, nullptr, 80);
    k_out<<<5056, 1024, 0, s2>>>(out, d1b, linW, linb, tgt);

    // ---- join ----
    cudaEventRecord(eE, s2);
    cudaStreamWaitEvent(0, eE, 0);
}

// round 10
// speedup vs baseline: 1.1937x; 1.0496x over previous
#include <cuda_runtime.h>

typedef unsigned long long ULL;

// ---------------- scratch (static device globals; no allocation) ----------------
static __device__ float g_gi[500 * 1024 * 300];     // 614.4 MB: encoder gi
static __device__ float g_gid[80 * 1024 * 300];     // 98.3 MB: decoder gi (both layers)
static __device__ float g_buf0[500 * 1024 * 100];   // 204.8 MB: encoder e0 sequence
static __device__ float g_bufd[80 * 1024 * 100];    // decoder d0 sequence
static __device__ float g_d1[80 * 1024 * 100];      // decoder layer-1 outputs
static __device__ float g_decin[80 * 1024 * 26];    // embedded decoder inputs
static __device__ float g_h0[1024 * 100];           // h_enc0
static __device__ float g_h1[1024 * 100];           // h_enc1

// ---------------- f32x2 helpers ----------------
__device__ __forceinline__ ULL pack2(float lo, float hi) {
    ULL r;
    asm("mov.b64 %0, {%1, %2};" : "=l"(r) : "f"(lo), "f"(hi));
    return r;
}
__device__ __forceinline__ void unpack2(ULL v, float& lo, float& hi) {
    asm("mov.b64 {%0, %1}, %2;" : "=f"(lo), "=f"(hi) : "l"(v));
}
__device__ __forceinline__ void fma2(ULL& d, ULL a, ULL b) {
    asm("fma.rn.f32x2 %0, %1, %2, %0;" : "+l"(d) : "l"(a), "l"(b));
}

// ---------------- accurate activations (immune to fast-math flags) ----------------
__device__ __forceinline__ float exp_acc(float x) {
    float z = x * 1.4426950408889634f;
    float n = rintf(z);
    float r = fmaf(n, -0.693147182464599609375f, x);
    r = fmaf(n, 1.9046542121259336e-9f, r);
    float p = 1.9841270114e-4f;
    p = fmaf(p, r, 1.3888888877e-3f);
    p = fmaf(p, r, 8.3333337680e-3f);
    p = fmaf(p, r, 4.1666667908e-2f);
    p = fmaf(p, r, 1.6666667163e-1f);
    p = fmaf(p, r, 0.5f);
    p = fmaf(p, r, 1.0f);
    p = fmaf(p, r, 1.0f);
    int i = (int)n;
    float sc = __int_as_float((i + 127) << 23);
    return p * sc;
}
__device__ __forceinline__ float sigm(float x) {
    float xc = fminf(fmaxf(x, -30.0f), 30.0f);
    float s = exp_acc(-xc);
    return __fdiv_rn(1.0f, 1.0f + s);
}
__device__ __forceinline__ float tanh_acc(float x) {
    float ax = fabsf(x);
    float t;
    if (ax < 0.25f) {
        float x2 = x * x;
        float p = 0.021869488536155203f;
        p = fmaf(p, x2, -0.05396825396825397f);
        p = fmaf(p, x2, 0.13333333333333333f);
        p = fmaf(p, x2, -0.3333333333333333f);
        p = fmaf(p, x2, 1.0f);
        t = x * p;
    } else {
        float a = fminf(ax, 9.0f);
        float s = exp_acc(-2.0f * a);
        t = __fdiv_rn(1.0f - s, 1.0f + s);
        t = copysignf(t, x);
    }
    return t;
}

// ---------------- embedding gather ----------------
__global__ void k_embed(const int* __restrict__ tgt,
                        const float* __restrict__ emb,
                        float* __restrict__ out) {
    int idx = blockIdx.x * blockDim.x + threadIdx.x;
    const int total = 80 * 1024 * 26;
    if (idx < total) {
        int e  = idx % 26;
        int pb = idx / 26;
        int t = tgt[pb] & 63;
        out[idx] = emb[t * 26 + e];
    }
}

// ---------------- gi GEMM (2D register tile + distance-1 smem prefetch) ----------------
template <int K>
__global__ void __launch_bounds__(256) k_gemm(float* __restrict__ gi,
                                              const float* __restrict__ x,
                                              const float* __restrict__ W,
                                              const float* __restrict__ bih,
                                              const float* __restrict__ bhh) {
    const int MP = 132;
    const int BP = 68;
    extern __shared__ float sm[];
    float* As = sm;                  // [K+1][132]
    float* Bs = sm + (K + 1) * MP;   // [K+1][68]

    const int tid = threadIdx.x;
    const long n0 = (long)blockIdx.x * 128;
    const int  j0 = blockIdx.y * 64;

    for (int idx = tid; idx < 128 * K; idx += 256) {
        int m = idx / K, k = idx - m * K;
        As[k * MP + m] = x[(n0 + m) * K + k];
    }
    for (int idx = tid; idx < 64 * K; idx += 256) {
        int jj = idx / K, k = idx - jj * K;
        int j = j0 + jj;
        Bs[k * BP + jj] = (j < 300) ? W[j * K + k] : 0.0f;
    }
    __syncthreads();

    const int cx = tid & 15;
    const int ry = tid >> 4;

    ULL acc[4][4];
#pragma unroll
    for (int c = 0; c < 4; c++) {
        int j = j0 + cx * 4 + c;
        float bj = 0.0f;
        if (j < 300) bj = bih[j] + ((j < 200) ? bhh[j] : 0.0f);
        ULL b2 = pack2(bj, bj);
#pragma unroll
        for (int rp = 0; rp < 4; rp++) acc[c][rp] = b2;
    }

    const float* abase = As + ry * 8;
    const float* bbase = Bs + cx * 4;

    ulonglong2 a01 = *(const ulonglong2*)(abase);
    ulonglong2 a23 = *(const ulonglong2*)(abase + 4);
    float4     b4  = *(const float4*)(bbase);
#pragma unroll 4
    for (int k = 0; k < K; k++) {
        ulonglong2 a01c = a01, a23c = a23;
        float4     b4c  = b4;
        a01 = *(const ulonglong2*)(abase + (k + 1) * MP);
        a23 = *(const ulonglong2*)(abase + (k + 1) * MP + 4);
        b4  = *(const float4*)(bbase + (k + 1) * BP);
#pragma unroll
        for (int c = 0; c < 4; c++) {
            float bc = (c == 0) ? b4c.x : (c == 1) ? b4c.y : (c == 2) ? b4c.z : b4c.w;
            ULL w2 = pack2(bc, bc);
            fma2(acc[c][0], a01c.x, w2);
            fma2(acc[c][1], a01c.y, w2);
            fma2(acc[c][2], a23c.x, w2);
            fma2(acc[c][3], a23c.y, w2);
        }
    }

    if (j0 + cx * 4 < 300) {
        float v[4][8];
#pragma unroll
        for (int c = 0; c < 4; c++)
#pragma unroll
            for (int rp = 0; rp < 4; rp++)
                unpack2(acc[c][rp], v[c][2 * rp], v[c][2 * rp + 1]);
#pragma unroll
        for (int r = 0; r < 8; r++) {
            float4 f;
            f.x = v[0][r]; f.y = v[1][r]; f.z = v[2][r]; f.w = v[3][r];
            *(float4*)(gi + (n0 + ry * 8 + r) * 300 + j0 + cx * 4) = f;
        }
    }
}

// ---------------- persistent GRU recurrence (W in regs, 4k-group pipeline) ----------------
// 147 blocks: block b<146 handles rows b*7..b*7+6 (nr=7), block 146 rows 1022..1023 (nr=2).
// 320 threads, 300 active: thread = column j, all block rows. BITWISE round-4 chains.
__global__ void __launch_bounds__(320) k_gru(const float* __restrict__ gi,
                                             const float* __restrict__ Whh,
                                             const float* __restrict__ bhh,
                                             const float* __restrict__ h0,
                                             float* __restrict__ y,
                                             float* __restrict__ hfin,
                                             int T) {
    __shared__ float hs[104 * 8];   // [k][8], k>=100 and unused rows stay 0
    __shared__ float rsT[800];      // [r][100]
    __shared__ float zsT[800];
    __shared__ float asT[800];
    __shared__ float bsT[800];

    const int tid = threadIdx.x;
    const int b0  = blockIdx.x * 7;
    const int nr  = (blockIdx.x == 146) ? 2 : 7;
    const bool active = tid < 300;
    const int j = active ? tid : 0;
    const int g = (j >= 200) ? 2 : (j >= 100) ? 1 : 0;
    const int u = j - g * 100;

    for (int idx = tid; idx < 832; idx += 320) {
        int r = idx & 7, k = idx >> 3;
        hs[idx] = (k < 100 && r < nr && h0) ? h0[(b0 + r) * 100 + k] : 0.0f;
    }

    // W row -> registers
    float wreg[100];
    {
        const float4* wp = (const float4*)(Whh + j * 100);
#pragma unroll
        for (int k4 = 0; k4 < 25; k4++) {
            float4 w = wp[k4];
            wreg[k4 * 4 + 0] = w.x;
            wreg[k4 * 4 + 1] = w.y;
            wreg[k4 * 4 + 2] = w.z;
            wreg[k4 * 4 + 3] = w.w;
        }
    }
    const float bnn = (active && g == 2) ? bhh[j] : 0.0f;

    // cross-step gi prefetch: gvc holds step t's values
    float gvc[8];
#pragma unroll
    for (int r = 0; r < 8; r++) gvc[r] = 0.0f;
    if (active) {
        const float* gp = gi + ((long)0 * 1024 + b0) * 300 + j;
        for (int r = 0; r < nr; r++) gvc[r] = gp[r * 300];
    }
    __syncthreads();

    for (int t = 0; t < T; t++) {
        float gvn[8];
#pragma unroll
        for (int r = 0; r < 8; r++) gvn[r] = 0.0f;
        if (active) {
            // issue next step's gi loads first (consumed next iteration)
            if (t + 1 < T) {
                const float* gp = gi + ((long)(t + 1) * 1024 + b0) * 300 + j;
                for (int r = 0; r < nr; r++) gvn[r] = gp[r * 300];
            }

            // matvec: lanes = row pairs, k-ascending chains; 4k-group pipeline
            ULL a01 = 0, a23 = 0, a45 = 0, a67 = 0;
            ulonglong2 nA[4], nB[4];
#pragma unroll
            for (int i = 0; i < 4; i++) {
                nA[i] = *(const ulonglong2*)(hs + i * 8);
                nB[i] = *(const ulonglong2*)(hs + i * 8 + 4);
            }
#pragma unroll
            for (int grp = 0; grp < 25; grp++) {
                ulonglong2 cA[4], cB[4];
#pragma unroll
                for (int i = 0; i < 4; i++) { cA[i] = nA[i]; cB[i] = nB[i]; }
                // prefetch group grp+1 (grp=24 -> k 100..103 zero pad, unused)
#pragma unroll
                for (int i = 0; i < 4; i++) {
                    nA[i] = *(const ulonglong2*)(hs + ((grp + 1) * 4 + i) * 8);
                    nB[i] = *(const ulonglong2*)(hs + ((grp + 1) * 4 + i) * 8 + 4);
                }
#pragma unroll
                for (int i = 0; i < 4; i++) {
                    ULL w2 = pack2(wreg[grp * 4 + i], wreg[grp * 4 + i]);
                    fma2(a01, cA[i].x, w2);
                    fma2(a23, cA[i].y, w2);
                    fma2(a45, cB[i].x, w2);
                    fma2(a67, cB[i].y, w2);
                }
            }
            float ah[8];
            unpack2(a01, ah[0], ah[1]);
            unpack2(a23, ah[2], ah[3]);
            unpack2(a45, ah[4], ah[5]);
            unpack2(a67, ah[6], ah[7]);

            if (g == 0) {
#pragma unroll
                for (int r = 0; r < 8; r++) rsT[r * 100 + u] = sigm(gvc[r] + ah[r]);
            } else if (g == 1) {
#pragma unroll
                for (int r = 0; r < 8; r++) zsT[r * 100 + u] = sigm(gvc[r] + ah[r]);
            } else {
#pragma unroll
                for (int r = 0; r < 8; r++) {
                    asT[r * 100 + u] = gvc[r];
                    bsT[r * 100 + u] = ah[r] + bnn;
                }
            }
        }
        __syncthreads();
        // Phase B: cells c = r*100+u over nr*100, coalesced in u
        if (active) {
            for (int c = tid; c < nr * 100; c += 300) {
                int r = c / 100, uu = c - r * 100;
                float rr = rsT[c];
                float zz = zsT[c];
                float av = asT[c];
                float bv = bsT[c];
                float ho = hs[uu * 8 + r];
                float nn = tanh_acc(fmaf(rr, bv, av));
                float hn = fmaf(zz, ho - nn, nn);
                hs[uu * 8 + r] = hn;
                if (y) y[((long)t * 1024 + b0 + r) * 100 + uu] = hn;
                if (hfin && t == T - 1) hfin[(b0 + r) * 100 + uu] = hn;
            }
        }
        __syncthreads();
#pragma unroll
        for (int r = 0; r < 8; r++) gvc[r] = gvn[r];
    }
}

// ---------------- logits + argmax + target_cal ----------------
__global__ void __launch_bounds__(1024) k_out(float* __restrict__ out,
                                              const float* __restrict__ d1,
                                              const float* __restrict__ W,
                                              const float* __restrict__ b,
                                              const int* __restrict__ tgt) {
    __shared__ float Ws[64 * 101];
    __shared__ float ds[16 * 100];
    __shared__ float ls[16 * 64];
    const int tid = threadIdx.x;

    for (int idx = tid; idx < 64 * 101; idx += 1024) {
        int d = idx / 101, k = idx - d * 101;
        Ws[idx] = (k < 100) ? W[d * 100 + k] : 0.0f;
    }
    const long r0 = (long)blockIdx.x * 16;
    for (int idx = tid; idx < 1600; idx += 1024) {
        int rr = idx / 100, k = idx - rr * 100;
        ds[idx] = d1[(r0 + rr) * 100 + k];
    }
    __syncthreads();

    const int rr = tid >> 6;
    const int d  = tid & 63;
    const float* dp = ds + rr * 100;
    const float* wp = Ws + d * 101;
    float a0 = b[d], a1 = 0.0f;
#pragma unroll 2
    for (int k = 0; k < 100; k += 2) {
        a0 = fmaf(dp[k],     wp[k],     a0);
        a1 = fmaf(dp[k + 1], wp[k + 1], a1);
    }
    float acc = a0 + a1;

    const long row = r0 + rr;
    out[row * 64 + d] = acc;
    ls[rr * 64 + d] = acc;
    __syncthreads();

    if (d == 0) {
        float best = ls[rr * 64];
        int bi = 0;
        for (int k = 1; k < 64; k++) {
            float v = ls[rr * 64 + k];
            if (v > best) { best = v; bi = k; }
        }
        out[5177344 + row] = (float)tgt[row + 1024];
        out[5258240 + row] = (float)bi;
    }
}

// ---------------- launch ----------------
extern "C" void kernel_launch(void* const* d_in, const int* in_sizes, int n_in,
                              void* d_out, int out_size) {
    const float* x     = (const float*)d_in[0];
    const int*   tgt   = (const int*)d_in[1];
    const float* emb   = (const float*)d_in[2];
    const float* eWih0 = (const float*)d_in[3];
    const float* eWhh0 = (const float*)d_in[4];
    const float* ebih0 = (const float*)d_in[5];
    const float* ebhh0 = (const float*)d_in[6];
    const float* eWih1 = (const float*)d_in[7];
    const float* eWhh1 = (const float*)d_in[8];
    const float* ebih1 = (const float*)d_in[9];
    const float* ebhh1 = (const float*)d_in[10];
    const float* dWih0 = (const float*)d_in[11];
    const float* dWhh0 = (const float*)d_in[12];
    const float* dbih0 = (const float*)d_in[13];
    const float* dbhh0 = (const float*)d_in[14];
    const float* dWih1 = (const float*)d_in[15];
    const float* dWhh1 = (const float*)d_in[16];
    const float* dbih1 = (const float*)d_in[17];
    const float* dbhh1 = (const float*)d_in[18];
    const float* linW  = (const float*)d_in[19];
    const float* linb  = (const float*)d_in[20];
    float* out = (float*)d_out;

    float *gi, *gid, *buf0, *bufd, *d1b, *decin, *h0b, *h1b;
    cudaGetSymbolAddress((void**)&gi,    g_gi);
    cudaGetSymbolAddress((void**)&gid,   g_gid);
    cudaGetSymbolAddress((void**)&buf0,  g_buf0);
    cudaGetSymbolAddress((void**)&bufd,  g_bufd);
    cudaGetSymbolAddress((void**)&d1b,   g_d1);
    cudaGetSymbolAddress((void**)&decin, g_decin);
    cudaGetSymbolAddress((void**)&h0b,   g_h0);
    cudaGetSymbolAddress((void**)&h1b,   g_h1);

    static cudaStream_t s2 = nullptr;
    static cudaEvent_t eF = nullptr, eH0 = nullptr, eH1 = nullptr, eE = nullptr;
    if (!s2) {
        cudaStreamCreateWithFlags(&s2, cudaStreamNonBlocking);
        cudaEventCreateWithFlags(&eF,  cudaEventDisableTiming);
        cudaEventCreateWithFlags(&eH0, cudaEventDisableTiming);
        cudaEventCreateWithFlags(&eH1, cudaEventDisableTiming);
        cudaEventCreateWithFlags(&eE,  cudaEventDisableTiming);
    }

    const int SMEM_G26  = ((26 + 1) * 132 + (26 + 1) * 68) * 4;     // 21,600 B
    const int SMEM_G100 = ((100 + 1) * 132 + (100 + 1) * 68) * 4;   // 80,800 B
    cudaFuncSetAttribute((const void*)k_gemm<26>,
                         cudaFuncAttributeMaxDynamicSharedMemorySize, SMEM_G26);
    cudaFuncSetAttribute((const void*)k_gemm<100>,
                         cudaFuncAttributeMaxDynamicSharedMemorySize, SMEM_G100);

    // ---- fork: decoder-independent prep on s2 ----
    cudaEventRecord(eF, 0);
    cudaStreamWaitEvent(s2, eF, 0);
    k_embed<<<(80 * 1024 * 26 + 255) / 256, 256, 0, s2>>>(tgt, emb, decin);
    k_gemm<26><<<dim3(640, 5), 256, SMEM_G26, s2>>>(gid, decin, dWih0, dbih0, dbhh0);

    // ---- encoder on capture stream ----
    k_gemm<26><<<dim3(4000, 5), 256, SMEM_G26>>>(gi, x, eWih0, ebih0, ebhh0);
    k_gru<<<147, 320>>>(gi, eWhh0, ebhh0, nullptr, buf0, h0b, 500);
    cudaEventRecord(eH0, 0);
    k_gemm<100><<<dim3(4000, 5), 256, SMEM_G100>>>(gi, buf0, eWih1, ebih1, ebhh1);
    k_gru<<<147, 320>>>(gi, eWhh1, ebhh1, nullptr, nullptr, h1b, 500);
    cudaEventRecord(eH1, 0);

    // ---- decoder on s2 (overlaps encoder layer 1) ----
    cudaStreamWaitEvent(s2, eH0, 0);
    k_gru<<<147, 320, 0, s2>>>(gid, dWhh0, dbhh0, h0b, bufd, nullptr, 80);
    k_gemm<100><<<dim3(640, 5), 256, SMEM_G100, s2>>>(gid, bufd, dWih1, dbih1, dbhh1);
    cudaStreamWaitEvent(s2, eH1, 0);
    k_gru<<<147, 320, 0, s2>>>(gid, dWhh1, dbhh1, h1b, d1b, nullptr, 80);
    k_out<<<5056, 1024, 0, s2>>>(out, d1b, linW, linb, tgt);

    // ---- join ----
    cudaEventRecord(eE, s2);
    cudaStreamWaitEvent(0, eE, 0);
}

// round 15
// speedup vs baseline: 1.2564x; 1.0525x over previous
#include <cuda_runtime.h>

typedef unsigned long long ULL;

// ---------------- scratch (static device globals; no allocation) ----------------
static __device__ float g_gi[500 * 1024 * 300];     // 614.4 MB: encoder gi
static __device__ float g_gid[80 * 1024 * 300];     // 98.3 MB: decoder gi (both layers)
static __device__ float g_buf0[500 * 1024 * 100];   // 204.8 MB: encoder e0 sequence
static __device__ float g_bufd[80 * 1024 * 100];    // decoder d0 sequence
static __device__ float g_d1[80 * 1024 * 100];      // decoder layer-1 outputs
static __device__ float g_decin[80 * 1024 * 26];    // embedded decoder inputs
static __device__ float g_h0[1024 * 100];           // h_enc0
static __device__ float g_h1[1024 * 100];           // h_enc1

// ---------------- f32x2 helpers ----------------
__device__ __forceinline__ ULL pack2(float lo, float hi) {
    ULL r;
    asm("mov.b64 %0, {%1, %2};" : "=l"(r) : "f"(lo), "f"(hi));
    return r;
}
__device__ __forceinline__ void unpack2(ULL v, float& lo, float& hi) {
    asm("mov.b64 {%0, %1}, %2;" : "=f"(lo), "=f"(hi) : "l"(v));
}
__device__ __forceinline__ void fma2(ULL& d, ULL a, ULL b) {
    asm("fma.rn.f32x2 %0, %1, %2, %0;" : "+l"(d) : "l"(a), "l"(b));
}

// ---------------- accurate activations (immune to fast-math flags) ----------------
__device__ __forceinline__ float exp_acc(float x) {
    float z = x * 1.4426950408889634f;
    float n = rintf(z);
    float r = fmaf(n, -0.693147182464599609375f, x);
    r = fmaf(n, 1.9046542121259336e-9f, r);
    float p = 1.9841270114e-4f;
    p = fmaf(p, r, 1.3888888877e-3f);
    p = fmaf(p, r, 8.3333337680e-3f);
    p = fmaf(p, r, 4.1666667908e-2f);
    p = fmaf(p, r, 1.6666667163e-1f);
    p = fmaf(p, r, 0.5f);
    p = fmaf(p, r, 1.0f);
    p = fmaf(p, r, 1.0f);
    int i = (int)n;
    float sc = __int_as_float((i + 127) << 23);
    return p * sc;
}
__device__ __forceinline__ float sigm(float x) {
    float xc = fminf(fmaxf(x, -30.0f), 30.0f);
    float s = exp_acc(-xc);
    return __fdiv_rn(1.0f, 1.0f + s);
}
__device__ __forceinline__ float tanh_acc(float x) {
    float ax = fabsf(x);
    float t;
    if (ax < 0.25f) {
        float x2 = x * x;
        float p = 0.021869488536155203f;
        p = fmaf(p, x2, -0.05396825396825397f);
        p = fmaf(p, x2, 0.13333333333333333f);
        p = fmaf(p, x2, -0.3333333333333333f);
        p = fmaf(p, x2, 1.0f);
        t = x * p;
    } else {
        float a = fminf(ax, 9.0f);
        float s = exp_acc(-2.0f * a);
        t = __fdiv_rn(1.0f - s, 1.0f + s);
        t = copysignf(t, x);
    }
    return t;
}

// ---------------- embedding gather ----------------
__global__ void k_embed(const int* __restrict__ tgt,
                        const float* __restrict__ emb,
                        float* __restrict__ out) {
    int idx = blockIdx.x * blockDim.x + threadIdx.x;
    const int total = 80 * 1024 * 26;
    if (idx < total) {
        int e  = idx % 26;
        int pb = idx / 26;
        int t = tgt[pb] & 63;
        out[idx] = emb[t * 26 + e];
    }
}

// ---------------- gi GEMM (2D register tile + distance-1 smem prefetch) ----------------
template <int K>
__global__ void __launch_bounds__(256) k_gemm(float* __restrict__ gi,
                                              const float* __restrict__ x,
                                              const float* __restrict__ W,
                                              const float* __restrict__ bih,
                                              const float* __restrict__ bhh) {
    const int MP = 132;
    const int BP = 68;
    extern __shared__ float sm[];
    float* As = sm;                  // [K+1][132]
    float* Bs = sm + (K + 1) * MP;   // [K+1][68]

    const int tid = threadIdx.x;
    const long n0 = (long)blockIdx.x * 128;
    const int  j0 = blockIdx.y * 64;

    for (int idx = tid; idx < 128 * K; idx += 256) {
        int m = idx / K, k = idx - m * K;
        As[k * MP + m] = x[(n0 + m) * K + k];
    }
    for (int idx = tid; idx < 64 * K; idx += 256) {
        int jj = idx / K, k = idx - jj * K;
        int j = j0 + jj;
        Bs[k * BP + jj] = (j < 300) ? W[j * K + k] : 0.0f;
    }
    __syncthreads();

    const int cx = tid & 15;
    const int ry = tid >> 4;

    ULL acc[4][4];
#pragma unroll
    for (int c = 0; c < 4; c++) {
        int j = j0 + cx * 4 + c;
        float bj = 0.0f;
        if (j < 300) bj = bih[j] + ((j < 200) ? bhh[j] : 0.0f);
        ULL b2 = pack2(bj, bj);
#pragma unroll
        for (int rp = 0; rp < 4; rp++) acc[c][rp] = b2;
    }

    const float* abase = As + ry * 8;
    const float* bbase = Bs + cx * 4;

    ulonglong2 a01 = *(const ulonglong2*)(abase);
    ulonglong2 a23 = *(const ulonglong2*)(abase + 4);
    float4     b4  = *(const float4*)(bbase);
#pragma unroll 4
    for (int k = 0; k < K; k++) {
        ulonglong2 a01c = a01, a23c = a23;
        float4     b4c  = b4;
        a01 = *(const ulonglong2*)(abase + (k + 1) * MP);
        a23 = *(const ulonglong2*)(abase + (k + 1) * MP + 4);
        b4  = *(const float4*)(bbase + (k + 1) * BP);
#pragma unroll
        for (int c = 0; c < 4; c++) {
            float bc = (c == 0) ? b4c.x : (c == 1) ? b4c.y : (c == 2) ? b4c.z : b4c.w;
            ULL w2 = pack2(bc, bc);
            fma2(acc[c][0], a01c.x, w2);
            fma2(acc[c][1], a01c.y, w2);
            fma2(acc[c][2], a23c.x, w2);
            fma2(acc[c][3], a23c.y, w2);
        }
    }

    if (j0 + cx * 4 < 300) {
        float v[4][8];
#pragma unroll
        for (int c = 0; c < 4; c++)
#pragma unroll
            for (int rp = 0; rp < 4; rp++)
                unpack2(acc[c][rp], v[c][2 * rp], v[c][2 * rp + 1]);
#pragma unroll
        for (int r = 0; r < 8; r++) {
            float4 f;
            f.x = v[0][r]; f.y = v[1][r]; f.z = v[2][r]; f.w = v[3][r];
            *(float4*)(gi + (n0 + ry * 8 + r) * 300 + j0 + cx * 4) = f;
        }
    }
}

// ---------------- persistent GRU recurrence (2 blocks/SM, <=4 rows/block) ----------------
// 296 blocks: b<136 -> rows 4b..4b+3 (nr=4); b>=136 -> rows 544+3(b-136).. (nr=3).
// 320 threads, 300 active: thread = column j. W: k<48 in regs, k>=48 in smem (stride 53).
// BITWISE round-4 chains: per row, bias + k-ascending fma; f32x2 lanes = row pairs.
__global__ void __launch_bounds__(320, 2) k_gru(const float* __restrict__ gi,
                                                const float* __restrict__ Whh,
                                                const float* __restrict__ bhh,
                                                const float* __restrict__ h0,
                                                float* __restrict__ y,
                                                float* __restrict__ hfin,
                                                int T) {
    extern __shared__ float sm[];
    float* hs  = sm;            // [104][4]: hs[k*4+r], k>=100 zero pad (prefetch overrun)
    float* rsT = sm + 416;      // [4][100] raw r-gate sums
    float* zsT = rsT + 400;     // [4][100] raw z-gate sums
    float* asT = zsT + 400;     // [4][100] n-gate input part
    float* bsT = asT + 400;     // [4][100] n-gate hidden part
    float* Ws2 = bsT + 400;     // [300][53]: W[j][48+k2], stride 53 (odd -> conflict-free)

    const int tid = threadIdx.x;
    const int bx  = blockIdx.x;
    const int b0  = (bx < 136) ? bx * 4 : 544 + (bx - 136) * 3;
    const int nr  = (bx < 136) ? 4 : 3;
    const bool active = tid < 300;
    const int j = active ? tid : 0;
    const int g = (j >= 200) ? 2 : (j >= 100) ? 1 : 0;
    const int u = j - g * 100;

    for (int idx = tid; idx < 416; idx += 320) {
        int r = idx & 3, k = idx >> 2;
        hs[idx] = (k < 100 && r < nr && h0) ? h0[(b0 + r) * 100 + k] : 0.0f;
    }
    for (int idx = tid; idx < 300 * 52; idx += 320) {
        int jj = idx / 52, k2 = idx - jj * 52;
        Ws2[jj * 53 + k2] = Whh[jj * 100 + 48 + k2];
    }

    // W[j][0..47] -> registers (Whh + j*100 floats = 400j bytes: 16B aligned)
    float wreg[48];
    {
        const float4* wp = (const float4*)(Whh + j * 100);
#pragma unroll
        for (int k4 = 0; k4 < 12; k4++) {
            float4 w = wp[k4];
            wreg[k4 * 4 + 0] = w.x;
            wreg[k4 * 4 + 1] = w.y;
            wreg[k4 * 4 + 2] = w.z;
            wreg[k4 * 4 + 3] = w.w;
        }
    }
    const float bnn = (active && g == 2) ? bhh[j] : 0.0f;
    const float* wsrow = Ws2 + j * 53 - 48;

    // cross-step gi prefetch
    float gvc[4];
#pragma unroll
    for (int r = 0; r < 4; r++) gvc[r] = 0.0f;
    if (active) {
        const float* gp = gi + ((long)0 * 1024 + b0) * 300 + j;
        for (int r = 0; r < nr; r++) gvc[r] = gp[r * 300];
    }
    __syncthreads();

    for (int t = 0; t < T; t++) {
        float gvn[4];
#pragma unroll
        for (int r = 0; r < 4; r++) gvn[r] = 0.0f;
        if (active) {
            if (t + 1 < T) {
                const float* gp = gi + ((long)(t + 1) * 1024 + b0) * 300 + j;
                for (int r = 0; r < nr; r++) gvn[r] = gp[r * 300];
            }

            // matvec: rows 0-3, lanes = row pairs; k-ascending chains; distance-2 prefetch
            ULL a01 = 0, a23 = 0;
            ulonglong2 h0v = *(const ulonglong2*)(hs + 0);
            ulonglong2 h1v = *(const ulonglong2*)(hs + 4);
#pragma unroll
            for (int kk = 0; kk < 50; kk++) {
                const int k0 = 2 * kk, k1 = 2 * kk + 1;
                ulonglong2 c0 = h0v, c1 = h1v;
                // prefetch k0+2, k1+2 (kk=49 -> k=100,101 zero pad, unused)
                h0v = *(const ulonglong2*)(hs + (k0 + 2) * 4);
                h1v = *(const ulonglong2*)(hs + (k1 + 2) * 4);
                float w0 = (k0 < 48) ? wreg[k0] : wsrow[k0];
                float w1 = (k1 < 48) ? wreg[k1] : wsrow[k1];
                ULL w2 = pack2(w0, w0);
                fma2(a01, c0.x, w2);
                fma2(a23, c0.y, w2);
                w2 = pack2(w1, w1);
                fma2(a01, c1.x, w2);
                fma2(a23, c1.y, w2);
            }
            float ah[4];
            unpack2(a01, ah[0], ah[1]);
            unpack2(a23, ah[2], ah[3]);

            // store RAW gate sums (activations deferred to phase B)
            if (g == 0) {
#pragma unroll
                for (int r = 0; r < 4; r++) rsT[r * 100 + u] = gvc[r] + ah[r];
            } else if (g == 1) {
#pragma unroll
                for (int r = 0; r < 4; r++) zsT[r * 100 + u] = gvc[r] + ah[r];
            } else {
#pragma unroll
                for (int r = 0; r < 4; r++) {
                    asT[r * 100 + u] = gvc[r];
                    bsT[r * 100 + u] = ah[r] + bnn;
                }
            }
        }
        __syncthreads();
        // Phase B: all activations + h update, distributed over 300 threads (<=2 cells)
        if (active) {
            for (int c = tid; c < nr * 100; c += 300) {
                int r = c / 100, uu = c - r * 100;
                float rr = sigm(rsT[c]);
                float zz = sigm(zsT[c]);
                float av = asT[c];
                float bv = bsT[c];
                float ho = hs[uu * 4 + r];
                float nn = tanh_acc(fmaf(rr, bv, av));
                float hn = fmaf(zz, ho - nn, nn);
                hs[uu * 4 + r] = hn;
                if (y) y[((long)t * 1024 + b0 + r) * 100 + uu] = hn;
                if (hfin && t == T - 1) hfin[(b0 + r) * 100 + uu] = hn;
            }
        }
        __syncthreads();
#pragma unroll
        for (int r = 0; r < 4; r++) gvc[r] = gvn[r];
    }
}

// ---------------- logits + argmax + target_cal ----------------
__global__ void __launch_bounds__(1024) k_out(float* __restrict__ out,
                                              const float* __restrict__ d1,
                                              const float* __restrict__ W,
                                              const float* __restrict__ b,
                                              const int* __restrict__ tgt) {
    __shared__ float Ws[64 * 101];
    __shared__ float ds[16 * 100];
    __shared__ float ls[16 * 64];
    const int tid = threadIdx.x;

    for (int idx = tid; idx < 64 * 101; idx += 1024) {
        int d = idx / 101, k = idx - d * 101;
        Ws[idx] = (k < 100) ? W[d * 100 + k] : 0.0f;
    }
    const long r0 = (long)blockIdx.x * 16;
    for (int idx = tid; idx < 1600; idx += 1024) {
        int rr = idx / 100, k = idx - rr * 100;
        ds[idx] = d1[(r0 + rr) * 100 + k];
    }
    __syncthreads();

    const int rr = tid >> 6;
    const int d  = tid & 63;
    const float* dp = ds + rr * 100;
    const float* wp = Ws + d * 101;
    float a0 = b[d], a1 = 0.0f;
#pragma unroll 2
    for (int k = 0; k < 100; k += 2) {
        a0 = fmaf(dp[k],     wp[k],     a0);
        a1 = fmaf(dp[k + 1], wp[k + 1], a1);
    }
    float acc = a0 + a1;

    const long row = r0 + rr;
    out[row * 64 + d] = acc;
    ls[rr * 64 + d] = acc;
    __syncthreads();

    if (d == 0) {
        float best = ls[rr * 64];
        int bi = 0;
        for (int k = 1; k < 64; k++) {
            float v = ls[rr * 64 + k];
            if (v > best) { best = v; bi = k; }
        }
        out[5177344 + row] = (float)tgt[row + 1024];
        out[5258240 + row] = (float)bi;
    }
}

// ---------------- launch ----------------
extern "C" void kernel_launch(void* const* d_in, const int* in_sizes, int n_in,
                              void* d_out, int out_size) {
    const float* x     = (const float*)d_in[0];
    const int*   tgt   = (const int*)d_in[1];
    const float* emb   = (const float*)d_in[2];
    const float* eWih0 = (const float*)d_in[3];
    const float* eWhh0 = (const float*)d_in[4];
    const float* ebih0 = (const float*)d_in[5];
    const float* ebhh0 = (const float*)d_in[6];
    const float* eWih1 = (const float*)d_in[7];
    const float* eWhh1 = (const float*)d_in[8];
    const float* ebih1 = (const float*)d_in[9];
    const float* ebhh1 = (const float*)d_in[10];
    const float* dWih0 = (const float*)d_in[11];
    const float* dWhh0 = (const float*)d_in[12];
    const float* dbih0 = (const float*)d_in[13];
    const float* dbhh0 = (const float*)d_in[14];
    const float* dWih1 = (const float*)d_in[15];
    const float* dWhh1 = (const float*)d_in[16];
    const float* dbih1 = (const float*)d_in[17];
    const float* dbhh1 = (const float*)d_in[18];
    const float* linW  = (const float*)d_in[19];
    const float* linb  = (const float*)d_in[20];
    float* out = (float*)d_out;

    float *gi, *gid, *buf0, *bufd, *d1b, *decin, *h0b, *h1b;
    cudaGetSymbolAddress((void**)&gi,    g_gi);
    cudaGetSymbolAddress((void**)&gid,   g_gid);
    cudaGetSymbolAddress((void**)&buf0,  g_buf0);
    cudaGetSymbolAddress((void**)&bufd,  g_bufd);
    cudaGetSymbolAddress((void**)&d1b,   g_d1);
    cudaGetSymbolAddress((void**)&decin, g_decin);
    cudaGetSymbolAddress((void**)&h0b,   g_h0);
    cudaGetSymbolAddress((void**)&h1b,   g_h1);

    static cudaStream_t s2 = nullptr;
    static cudaEvent_t eF = nullptr, eH0 = nullptr, eH1 = nullptr, eE = nullptr;
    if (!s2) {
        cudaStreamCreateWithFlags(&s2, cudaStreamNonBlocking);
        cudaEventCreateWithFlags(&eF,  cudaEventDisableTiming);
        cudaEventCreateWithFlags(&eH0, cudaEventDisableTiming);
        cudaEventCreateWithFlags(&eH1, cudaEventDisableTiming);
        cudaEventCreateWithFlags(&eE,  cudaEventDisableTiming);
    }

    const int SMEM_G26  = ((26 + 1) * 132 + (26 + 1) * 68) * 4;     // 21,600 B
    const int SMEM_G100 = ((100 + 1) * 132 + (100 + 1) * 68) * 4;   // 80,800 B
    const int SMEM_GRU  = (416 + 4 * 400 + 300 * 53) * 4;           // 71,664 B (x2/SM fits)
    cudaFuncSetAttribute((const void*)k_gemm<26>,
                         cudaFuncAttributeMaxDynamicSharedMemorySize, SMEM_G26);
    cudaFuncSetAttribute((const void*)k_gemm<100>,
                         cudaFuncAttributeMaxDynamicSharedMemorySize, SMEM_G100);
    cudaFuncSetAttribute((const void*)k_gru,
                         cudaFuncAttributeMaxDynamicSharedMemorySize, SMEM_GRU);

    // ---- fork: decoder-independent prep on s2 ----
    cudaEventRecord(eF, 0);
    cudaStreamWaitEvent(s2, eF, 0);
    k_embed<<<(80 * 1024 * 26 + 255) / 256, 256, 0, s2>>>(tgt, emb, decin);
    k_gemm<26><<<dim3(640, 5), 256, SMEM_G26, s2>>>(gid, decin, dWih0, dbih0, dbhh0);

    // ---- encoder on capture stream ----
    k_gemm<26><<<dim3(4000, 5), 256, SMEM_G26>>>(gi, x, eWih0, ebih0, ebhh0);
    k_gru<<<296, 320, SMEM_GRU>>>(gi, eWhh0, ebhh0, nullptr, buf0, h0b, 500);
    cudaEventRecord(eH0, 0);
    k_gemm<100><<<dim3(4000, 5), 256, SMEM_G100>>>(gi, buf0, eWih1, ebih1, ebhh1);
    k_gru<<<296, 320, SMEM_GRU>>>(gi, eWhh1, ebhh1, nullptr, nullptr, h1b, 500);
    cudaEventRecord(eH1, 0);

    // ---- decoder on s2 (overlaps encoder layer 1) ----
    cudaStreamWaitEvent(s2, eH0, 0);
    k_gru<<<296, 320, SMEM_GRU, s2>>>(gid, dWhh0, dbhh0, h0b, bufd, nullptr, 80);
    k_gemm<100><<<dim3(640, 5), 256, SMEM_G100, s2>>>(gid, bufd, dWih1, dbih1, dbhh1);
    cudaStreamWaitEvent(s2, eH1, 0);
    k_gru<<<296, 320, SMEM_GRU, s2>>>(gid, dWhh1, dbhh1, h1b, d1b, nullptr, 80);
    k_out<<<5056, 1024, 0, s2>>>(out, d1b, linW, linb, tgt);

    // ---- join ----
    cudaEventRecord(eE, s2);
    cudaStreamWaitEvent(0, eE, 0);
}